// round 1
// baseline (speedup 1.0000x reference)
#include <cuda_runtime.h>

#define N_NODES 10000
#define N_EDGES 640000
#define K_DIM   128

// ---------------- scratch (static device allocations are allowed) -------------
__device__ __align__(128) int   g_deg[N_NODES];
__device__ __align__(128) int   g_off[N_NODES + 1];
__device__ __align__(128) int   g_pos[N_NODES];
__device__ __align__(128) int   g_csr[N_EDGES];
__device__ __align__(128) float g_y [N_NODES * 256];   // fused [neigh|self] projections
__device__ __align__(128) float g_h0[N_NODES * 128];
__device__ __align__(128) float g_h1[N_NODES * 128];

// ---------------- CSR build ---------------------------------------------------
__global__ void zero_deg_k() {
    int i = blockIdx.x * blockDim.x + threadIdx.x;
    if (i < N_NODES) g_deg[i] = 0;
}

__global__ void hist_k(const int* __restrict__ dst) {
    int e = blockIdx.x * blockDim.x + threadIdx.x;
    if (e < N_EDGES) atomicAdd(&g_deg[dst[e]], 1);
}

__global__ void scan_k() {
    __shared__ int s[1024];
    __shared__ int carry;
    int tid = threadIdx.x;
    if (tid == 0) carry = 0;
    __syncthreads();
    for (int base = 0; base < N_NODES; base += 1024) {
        int idx = base + tid;
        int v = (idx < N_NODES) ? g_deg[idx] : 0;
        s[tid] = v;
        __syncthreads();
        #pragma unroll
        for (int ofs = 1; ofs < 1024; ofs <<= 1) {
            int t = 0;
            if (tid >= ofs) t = s[tid - ofs];
            __syncthreads();
            s[tid] += t;
            __syncthreads();
        }
        int excl = carry + s[tid] - v;
        if (idx < N_NODES) { g_off[idx] = excl; g_pos[idx] = excl; }
        __syncthreads();
        if (tid == 0) carry += s[1023];
        __syncthreads();
    }
    if (tid == 0) g_off[N_NODES] = carry;
}

__global__ void scatter_k(const int* __restrict__ src, const int* __restrict__ dst) {
    int e = blockIdx.x * blockDim.x + threadIdx.x;
    if (e < N_EDGES) {
        int d = dst[e];
        int p = atomicAdd(&g_pos[d], 1);
        g_csr[p] = src[e];
    }
}

// ---------------- fused dual GEMM: Y = X @ [W_neigh | W_self] -----------------
// X: [N_NODES, 128] row-major; Wn/Ws: [128, DOUT] row-major; Y: [N_NODES, 2*DOUT].
template <int DOUT>
__global__ void gemm_dual_k(const float* __restrict__ X,
                            const float* __restrict__ Wn,
                            const float* __restrict__ Ws,
                            float* __restrict__ Y) {
    constexpr int NOUT = 2 * DOUT;
    constexpr int BM = 64, BN = 64, BK = 16;
    __shared__ float As[BK][BM + 4];   // +4 pad keeps float4 alignment, breaks conflicts
    __shared__ float Bs[BK][BN];

    const int tid  = threadIdx.x;
    const int row0 = blockIdx.x * BM;
    const int col0 = blockIdx.y * BN;                 // global column in [0, NOUT)
    const float* W = (col0 < DOUT) ? (Wn + col0) : (Ws + (col0 - DOUT));

    const int tx = tid & 15, ty = tid >> 4;
    // A-tile load mapping: 64 rows x 16 k, float4 per thread
    const int lm = tid >> 2;
    const int lk = (tid & 3) * 4;
    // B-tile load mapping: 16 k-rows x 64 cols, float4 per thread
    const int bk = tid >> 4;
    const int bc = (tid & 15) * 4;

    float acc[4][4] = {};

    for (int k0 = 0; k0 < K_DIM; k0 += BK) {
        int gr = row0 + lm;
        float4 av = make_float4(0.f, 0.f, 0.f, 0.f);
        if (gr < N_NODES)
            av = *(const float4*)(X + (size_t)gr * K_DIM + k0 + lk);
        As[lk + 0][lm] = av.x; As[lk + 1][lm] = av.y;
        As[lk + 2][lm] = av.z; As[lk + 3][lm] = av.w;

        float4 bv = *(const float4*)(W + (size_t)(k0 + bk) * DOUT + bc);
        *(float4*)&Bs[bk][bc] = bv;
        __syncthreads();

        #pragma unroll
        for (int k = 0; k < BK; k++) {
            float4 a = *(const float4*)&As[k][ty * 4];
            float4 b = *(const float4*)&Bs[k][tx * 4];
            float ar[4] = {a.x, a.y, a.z, a.w};
            float br[4] = {b.x, b.y, b.z, b.w};
            #pragma unroll
            for (int i = 0; i < 4; i++)
                #pragma unroll
                for (int j = 0; j < 4; j++)
                    acc[i][j] += ar[i] * br[j];
        }
        __syncthreads();
    }

    #pragma unroll
    for (int i = 0; i < 4; i++) {
        int r = row0 + ty * 4 + i;
        if (r < N_NODES) {
            float4 o = make_float4(acc[i][0], acc[i][1], acc[i][2], acc[i][3]);
            *(float4*)&Y[(size_t)r * NOUT + col0 + tx * 4] = o;
        }
    }
}

// ---------------- aggregate: out = relu?(mean_neigh + self + bias) ------------
// One warp per node. Y rows are [neigh_proj(DOUT) | self_proj(DOUT)].
template <int DOUT, bool RELU>
__global__ void aggregate_k(const float* __restrict__ Y,
                            const float* __restrict__ bias,
                            float* __restrict__ out) {
    constexpr int NOUT = 2 * DOUT;
    constexpr int V = DOUT / 32;                      // floats per lane (4 or 2)
    int gw = (blockIdx.x * blockDim.x + threadIdx.x) >> 5;
    if (gw >= N_NODES) return;
    int lane = threadIdx.x & 31;

    int beg = g_off[gw], end = g_off[gw + 1];
    float acc0[V], acc1[V];
    #pragma unroll
    for (int v = 0; v < V; v++) { acc0[v] = 0.f; acc1[v] = 0.f; }

    const float* base = Y + lane * V;
    int j = beg;
    for (; j + 2 <= end; j += 2) {
        int s0 = __ldg(&g_csr[j]);
        int s1 = __ldg(&g_csr[j + 1]);
        if constexpr (V == 4) {
            float4 a = *(const float4*)(base + (size_t)s0 * NOUT);
            float4 b = *(const float4*)(base + (size_t)s1 * NOUT);
            acc0[0] += a.x; acc0[1] += a.y; acc0[2] += a.z; acc0[3] += a.w;
            acc1[0] += b.x; acc1[1] += b.y; acc1[2] += b.z; acc1[3] += b.w;
        } else {
            float2 a = *(const float2*)(base + (size_t)s0 * NOUT);
            float2 b = *(const float2*)(base + (size_t)s1 * NOUT);
            acc0[0] += a.x; acc0[1] += a.y;
            acc1[0] += b.x; acc1[1] += b.y;
        }
    }
    if (j < end) {
        int s0 = __ldg(&g_csr[j]);
        if constexpr (V == 4) {
            float4 a = *(const float4*)(base + (size_t)s0 * NOUT);
            acc0[0] += a.x; acc0[1] += a.y; acc0[2] += a.z; acc0[3] += a.w;
        } else {
            float2 a = *(const float2*)(base + (size_t)s0 * NOUT);
            acc0[0] += a.x; acc0[1] += a.y;
        }
    }

    float inv = 1.0f / fmaxf((float)(end - beg), 1.0f);
    float res[V];
    #pragma unroll
    for (int v = 0; v < V; v++) res[v] = (acc0[v] + acc1[v]) * inv;

    if constexpr (V == 4) {
        float4 s  = *(const float4*)(Y + (size_t)gw * NOUT + DOUT + lane * 4);
        float4 bb = *(const float4*)(bias + lane * 4);
        float4 o;
        o.x = res[0] + s.x + bb.x;
        o.y = res[1] + s.y + bb.y;
        o.z = res[2] + s.z + bb.z;
        o.w = res[3] + s.w + bb.w;
        if (RELU) {
            o.x = fmaxf(o.x, 0.f); o.y = fmaxf(o.y, 0.f);
            o.z = fmaxf(o.z, 0.f); o.w = fmaxf(o.w, 0.f);
        }
        *(float4*)(out + (size_t)gw * DOUT + lane * 4) = o;
    } else {
        float2 s  = *(const float2*)(Y + (size_t)gw * NOUT + DOUT + lane * 2);
        float2 bb = *(const float2*)(bias + lane * 2);
        float2 o;
        o.x = res[0] + s.x + bb.x;
        o.y = res[1] + s.y + bb.y;
        if (RELU) { o.x = fmaxf(o.x, 0.f); o.y = fmaxf(o.y, 0.f); }
        *(float2*)(out + (size_t)gw * DOUT + lane * 2) = o;
    }
}

// ---------------- launcher -----------------------------------------------------
extern "C" void kernel_launch(void* const* d_in, const int* in_sizes, int n_in,
                              void* d_out, int out_size) {
    const float* inputs  = (const float*)d_in[0];
    const float* W_self0 = (const float*)d_in[1];
    const float* W_nei0  = (const float*)d_in[2];
    const float* b0      = (const float*)d_in[3];
    const float* W_self1 = (const float*)d_in[4];
    const float* W_nei1  = (const float*)d_in[5];
    const float* b1      = (const float*)d_in[6];
    const float* W_self2 = (const float*)d_in[7];
    const float* W_nei2  = (const float*)d_in[8];
    const float* b2      = (const float*)d_in[9];
    const int* edge_src  = (const int*)d_in[10];
    const int* edge_dst  = (const int*)d_in[11];
    float* out = (float*)d_out;

    float *y, *h0, *h1;
    cudaGetSymbolAddress((void**)&y,  g_y);
    cudaGetSymbolAddress((void**)&h0, g_h0);
    cudaGetSymbolAddress((void**)&h1, g_h1);

    // CSR build (recomputed every launch; deterministic work)
    zero_deg_k<<<(N_NODES + 255) / 256, 256>>>();
    hist_k<<<(N_EDGES + 255) / 256, 256>>>(edge_dst);
    scan_k<<<1, 1024>>>();
    scatter_k<<<(N_EDGES + 255) / 256, 256>>>(edge_src, edge_dst);

    const int gm = (N_NODES + 63) / 64;          // 157
    const int agg_blocks = (N_NODES + 7) / 8;    // 1250 (8 warps / block)

    // layer 0: 128 -> 128, relu
    gemm_dual_k<128><<<dim3(gm, 4), 256>>>(inputs, W_nei0, W_self0, y);
    aggregate_k<128, true><<<agg_blocks, 256>>>(y, b0, h0);

    // layer 1: 128 -> 128, relu
    gemm_dual_k<128><<<dim3(gm, 4), 256>>>(h0, W_nei1, W_self1, y);
    aggregate_k<128, true><<<agg_blocks, 256>>>(y, b1, h1);

    // layer 2: 128 -> 64, no relu, straight to d_out
    gemm_dual_k<64><<<dim3(gm, 2), 256>>>(h1, W_nei2, W_self2, y);
    aggregate_k<64, false><<<agg_blocks, 256>>>(y, b2, out);

    (void)in_sizes; (void)n_in; (void)out_size;
}